// round 14
// baseline (speedup 1.0000x reference)
#include <cuda_runtime.h>
#include <cuda_bf16.h>
#include <cstdint>

#define Bn 1024
#define Sn 128
#define Dn 768
#define Cn 56
#define KC 16
#define NCHUNK 48
#define NBUF 7
#define AST (Sn * KC)                 /* floats per A stage = 2048 (8KB) */
#define A_BYTES (NBUF * AST * 4)      /* 57344 */
#define SMEM_DYN A_BYTES

// Fragment-major packed weights: Wp[ci][j][lane] = uint2 B-fragment for
// mma j at chunk ci. lane=(g<<2)|t4, c=8j+g, k0=16ci+4t4:
//   .x = bf16x2(W[c][k0],W[c][k0+1]), .y = bf16x2(W[c][k0+2],W[c][k0+3])
// One warp's (ci,j) read = 32 lanes x 8B = 256B contiguous, coalesced.
__device__ uint2 g_Wp[NCHUNK * 7 * 32];

__device__ __forceinline__ float wval(const float* w2, const float* w3,
                                      const float* w4, const float* w5,
                                      int c, int d) {
    if (c < 8)       { int f = c / 2;        int j = c % 2;        return w2[(f * Dn + d) * 2 + j]; }
    else if (c < 20) { int cc = c - 8;  int f = cc / 3; int j = cc % 3; return w3[(f * Dn + d) * 3 + j]; }
    else if (c < 36) { int cc = c - 20; int f = cc / 4; int j = cc % 4; return w4[(f * Dn + d) * 4 + j]; }
    else             { int cc = c - 36; int f = cc / 5; int j = cc % 5; return w5[(f * Dn + d) * 5 + j]; }
}

__device__ __forceinline__ uint32_t f2bf2(float lo, float hi) {
    __nv_bfloat162 h = __float22bfloat162_rn(make_float2(lo, hi));
    return *reinterpret_cast<uint32_t*>(&h);
}

__global__ void build_wp_kernel(const float* __restrict__ w2, const float* __restrict__ w3,
                                const float* __restrict__ w4, const float* __restrict__ w5) {
    int i = blockIdx.x * blockDim.x + threadIdx.x;
    if (i >= NCHUNK * 7 * 32) return;
    int ci = i / 224, rem = i % 224;
    int j = rem / 32, lane = rem % 32;
    int g = lane >> 2, t4 = lane & 3;
    int c = 8 * j + g;
    int k0 = ci * KC + 4 * t4;
    uint2 v;
    v.x = f2bf2(wval(w2, w3, w4, w5, c, k0),     wval(w2, w3, w4, w5, c, k0 + 1));
    v.y = f2bf2(wval(w2, w3, w4, w5, c, k0 + 2), wval(w2, w3, w4, w5, c, k0 + 3));
    g_Wp[i] = v;
}

__device__ __forceinline__ void cp16(uint32_t dst_smem, const void* src) {
    asm volatile("cp.async.cg.shared.global [%0], [%1], 16;\n" :: "r"(dst_smem), "l"(src));
}

__global__ __launch_bounds__(256, 4) void fused_kernel(
    const int* __restrict__ x, const float* __restrict__ hidden,
    const float* __restrict__ b2, const float* __restrict__ b3,
    const float* __restrict__ b4, const float* __restrict__ b5,
    const float* __restrict__ fcw, const float* __restrict__ fcb,
    float* __restrict__ out)
{
    extern __shared__ __align__(16) unsigned char sraw[];
    float* As = reinterpret_cast<float*>(sraw);                       // [NBUF][128][16]
    float (*Psm)[Cn + 1] = reinterpret_cast<float (*)[Cn + 1]>(sraw); // epilogue reuse (29.2KB)

    __shared__ int order[Sn];
    __shared__ unsigned mask4[4];
    __shared__ int sh_len;
    __shared__ float feats[16];

    const int b    = blockIdx.x;
    const int tid  = threadIdx.x;
    const int warp = tid >> 5;
    const int lane = tid & 31;
    const int g    = lane >> 2;   // 0..7
    const int t4   = lane & 3;    // 0..3

    const uint32_t a_base = (uint32_t)__cvta_generic_to_shared(As);
    const float* hidb = hidden + (long)b * Sn * Dn;

    // hoisted CTA-wide A staging offsets: 512 16B pieces, 2 per thread
    const int  ar0 = tid >> 2, aq0 = tid & 3;
    const uint32_t a_d0 = (uint32_t)(ar0 * KC + 4 * aq0) * 4;
    const uint32_t a_d1 = a_d0 + (uint32_t)(64 * KC) * 4;
    const long a_o0 = (long)ar0 * Dn + 4 * aq0;
    const long a_o1 = a_o0 + 64L * Dn;

    auto issueA = [&](int ci, int buf) {
        const float* hsrc = hidb + ci * KC;
        cp16(a_base + (uint32_t)(buf * AST * 4) + a_d0, hsrc + a_o0);
        cp16(a_base + (uint32_t)(buf * AST * 4) + a_d1, hsrc + a_o1);
        asm volatile("cp.async.commit_group;\n");
    };

    issueA(0, 0); issueA(1, 1); issueA(2, 2); issueA(3, 3); issueA(4, 4);

    // ---- stable compaction order (overlaps with first loads) ----
    if (tid < Sn) {
        int nz = (x[b * Sn + tid] != 0);
        unsigned m = __ballot_sync(0xFFFFFFFFu, nz);
        if (lane == 0) mask4[warp] = m;
    }
    __syncthreads();
    if (tid < Sn) {
        unsigned mw = mask4[warp];
        int nzbefore = __popc(mw & ((1u << lane) - 1u));
        int nztot_before = 0, total = 0;
        #pragma unroll
        for (int w = 0; w < 4; w++) { if (w < warp) nztot_before += __popc(mask4[w]); total += __popc(mask4[w]); }
        int isnz = (mw >> lane) & 1;
        int pos = isnz ? (nztot_before + nzbefore)
                       : (total + (tid - nztot_before - nzbefore));
        order[pos] = tid;
        if (tid == 0) sh_len = total;
    }

    // ---- GEMM mainloop: 48 chunks, 7 buffers, TWO chunks per barrier ----
    float acc[7][4];
    #pragma unroll
    for (int j = 0; j < 7; j++)
        #pragma unroll
        for (int q = 0; q < 4; q++) acc[j][q] = 0.0f;

    const int rowA = warp * 16 + g;
    const uint32_t a_off0 = (uint32_t)(rowA * KC + 4 * t4);
    const uint32_t a_off1 = a_off0 + 8 * KC;
    const uint2* wp_lane = g_Wp + lane;       // + (ci*7 + j)*32

    auto computeChunk = [&](int buf, int ci) {
        const float* Abuf = As + buf * AST;
        float4 f0 = *(const float4*)(Abuf + a_off0);
        float4 f1 = *(const float4*)(Abuf + a_off1);
        uint32_t a0 = f2bf2(f0.x, f0.y), a2 = f2bf2(f0.z, f0.w);
        uint32_t a1 = f2bf2(f1.x, f1.y), a3 = f2bf2(f1.z, f1.w);
        const uint2* wp = wp_lane + (ci * 7) * 32;
        #pragma unroll
        for (int j = 0; j < 7; j++) {
            uint2 bb = __ldg(wp + j * 32);
            asm volatile(
                "mma.sync.aligned.m16n8k16.row.col.f32.bf16.bf16.f32 "
                "{%0,%1,%2,%3}, {%4,%5,%6,%7}, {%8,%9}, {%0,%1,%2,%3};\n"
                : "+f"(acc[j][0]), "+f"(acc[j][1]), "+f"(acc[j][2]), "+f"(acc[j][3])
                : "r"(a0), "r"(a1), "r"(a2), "r"(a3), "r"(bb.x), "r"(bb.y));
        }
    };

    int buf = 0, bufN = 5;   // buf = ci%7 ; bufN = (ci+5)%7
    #pragma unroll 1
    for (int ci = 0; ci <= 40; ci += 2) {
        asm volatile("cp.async.wait_group 3;\n" ::: "memory");
        __syncthreads();
        issueA(ci + 5, bufN); if (++bufN == NBUF) bufN = 0;
        issueA(ci + 6, bufN); if (++bufN == NBUF) bufN = 0;
        computeChunk(buf, ci);     if (++buf == NBUF) buf = 0;
        computeChunk(buf, ci + 1); if (++buf == NBUF) buf = 0;
    }
    // tail: ci = 42, 44, 46   (42%7 == 0)
    asm volatile("cp.async.wait_group 3;\n" ::: "memory");
    __syncthreads();
    issueA(47, 5);
    computeChunk(0, 42); computeChunk(1, 43);
    asm volatile("cp.async.wait_group 2;\n" ::: "memory");
    __syncthreads();
    computeChunk(2, 44); computeChunk(3, 45);
    asm volatile("cp.async.wait_group 0;\n" ::: "memory");
    __syncthreads();
    computeChunk(4, 46); computeChunk(5, 47);

    // ---- all warps done with As before Psm overwrites it ----
    __syncthreads();
    #pragma unroll
    for (int j = 0; j < 7; j++) {
        int c = j * 8 + 2 * t4;
        Psm[rowA][c]         = acc[j][0];
        Psm[rowA][c + 1]     = acc[j][1];
        Psm[rowA + 8][c]     = acc[j][2];
        Psm[rowA + 8][c + 1] = acc[j][3];
    }
    __syncthreads();

    // ---- ragged conv + max-pool: 16 features, 2 per warp ----
    const int L = sh_len;
    #pragma unroll
    for (int r = 0; r < 2; r++) {
        int fi = warp + r * 8;
        int kk = fi / 4 + 2;
        int f  = fi % 4;
        int cb = (kk == 2 ? 0 : (kk == 3 ? 8 : (kk == 4 ? 20 : 36))) + f * kk;
        const float* bptr = (kk == 2 ? b2 : (kk == 3 ? b3 : (kk == 4 ? b4 : b5)));
        float bias = bptr[f];
        int nt = L - kk + 1;
        float m = -1e30f;
        for (int tp = lane; tp < nt; tp += 32) {
            float sconv = bias;
            for (int j = 0; j < kk; j++)
                sconv += Psm[order[tp + j]][cb + j];
            m = fmaxf(m, sconv);
        }
        #pragma unroll
        for (int off = 16; off; off >>= 1)
            m = fmaxf(m, __shfl_xor_sync(0xFFFFFFFFu, m, off));
        if (lane == 0) feats[fi] = m;
    }
    __syncthreads();

    if (tid == 0) {
        float z = fcb[0];
        #pragma unroll
        for (int i = 0; i < 16; i++) z += feats[i] * fcw[i];
        out[b] = 1.0f / (1.0f + expf(-z));
    }
}

extern "C" void kernel_launch(void* const* d_in, const int* in_sizes, int n_in,
                              void* d_out, int out_size) {
    const int*   x      = (const int*)d_in[0];
    const float* hidden = (const float*)d_in[1];
    const float* w2     = (const float*)d_in[2];
    const float* b2     = (const float*)d_in[3];
    const float* w3     = (const float*)d_in[4];
    const float* b3     = (const float*)d_in[5];
    const float* w4     = (const float*)d_in[6];
    const float* b4     = (const float*)d_in[7];
    const float* w5     = (const float*)d_in[8];
    const float* b5     = (const float*)d_in[9];
    const float* fcw    = (const float*)d_in[10];
    const float* fcb    = (const float*)d_in[11];
    float* out = (float*)d_out;

    cudaFuncSetAttribute(fused_kernel, cudaFuncAttributeMaxDynamicSharedMemorySize, SMEM_DYN);

    build_wp_kernel<<<(NCHUNK * 7 * 32 + 255) / 256, 256>>>(w2, w3, w4, w5);
    fused_kernel<<<Bn, 256, SMEM_DYN>>>(x, hidden, b2, b3, b4, b5, fcw, fcb, out);
}

// round 15
// speedup vs baseline: 1.2824x; 1.2824x over previous
#include <cuda_runtime.h>
#include <cuda_bf16.h>
#include <cstdint>

#define Bn 1024
#define Sn 128
#define Dn 768
#define Cn 56
#define KC 16
#define NCHUNK 48
#define NBUF 5
#define THREADS 512
#define ROWS2 256                     /* 2 batch rows per CTA */
#define AST (ROWS2 * KC)              /* floats per A stage = 4096 (16KB) */
#define BROW 16                       /* bf16 per B row, 32B stride */
#define BST (Cn * BROW)               /* 896 bf16 per B stage */
#define A_BYTES (NBUF * AST * 4)      /* 81920 */
#define B_BYTES (NBUF * BST * 2)      /* 8960  */
#define SMEM_DYN (A_BYTES + B_BYTES)  /* 90880 -> 2 CTAs/SM */

// Raw bf16 weight matrix W[c][k], physical k order.
// Fragment mapping: a0/bb.x <-> phys cols {4t4,4t4+1}, a2/bb.y <-> {4t4+2,4t4+3}.
__device__ __nv_bfloat16 g_Wb[Cn * Dn];

__global__ void build_w_kernel(const float* __restrict__ w2, const float* __restrict__ w3,
                               const float* __restrict__ w4, const float* __restrict__ w5) {
    int i = blockIdx.x * blockDim.x + threadIdx.x;
    if (i >= Cn * Dn) return;
    int c = i / Dn, d = i % Dn;
    float v;
    if (c < 8)       { int f = c / 2;        int j = c % 2;        v = w2[(f * Dn + d) * 2 + j]; }
    else if (c < 20) { int cc = c - 8;  int f = cc / 3; int j = cc % 3; v = w3[(f * Dn + d) * 3 + j]; }
    else if (c < 36) { int cc = c - 20; int f = cc / 4; int j = cc % 4; v = w4[(f * Dn + d) * 4 + j]; }
    else             { int cc = c - 36; int f = cc / 5; int j = cc % 5; v = w5[(f * Dn + d) * 5 + j]; }
    g_Wb[c * Dn + d] = __float2bfloat16(v);
}

__device__ __forceinline__ uint32_t f2bf2(float lo, float hi) {
    __nv_bfloat162 h = __float22bfloat162_rn(make_float2(lo, hi));
    return *reinterpret_cast<uint32_t*>(&h);
}

__device__ __forceinline__ void cp16(uint32_t dst_smem, const void* src) {
    asm volatile("cp.async.cg.shared.global [%0], [%1], 16;\n" :: "r"(dst_smem), "l"(src));
}

__global__ __launch_bounds__(THREADS, 2) void fused_kernel(
    const int* __restrict__ x, const float* __restrict__ hidden,
    const float* __restrict__ b2, const float* __restrict__ b3,
    const float* __restrict__ b4, const float* __restrict__ b5,
    const float* __restrict__ fcw, const float* __restrict__ fcb,
    float* __restrict__ out)
{
    extern __shared__ __align__(16) unsigned char sraw[];
    float* As = reinterpret_cast<float*>(sraw);                            // [NBUF][256][16]
    __nv_bfloat16* Bsm = reinterpret_cast<__nv_bfloat16*>(sraw + A_BYTES); // [NBUF][56][16]
    float (*Psm)[Cn + 1] = reinterpret_cast<float (*)[Cn + 1]>(sraw);      // epilogue reuse (58.4KB < 80KB)

    __shared__ int order2[2][Sn];
    __shared__ unsigned maskw[8];
    __shared__ int sh_len2[2];
    __shared__ float feats2[2][16];

    const int tid  = threadIdx.x;
    const int warp = tid >> 5;     // 0..15
    const int lane = tid & 31;
    const int g    = lane >> 2;    // 0..7
    const int t4   = lane & 3;     // 0..3

    const uint32_t a_base = (uint32_t)__cvta_generic_to_shared(As);
    const uint32_t b_base = (uint32_t)__cvta_generic_to_shared(Bsm);

    const int b0 = 2 * blockIdx.x;

    // ---- hoisted staging offsets: 1024 16B pieces per stage, 2 per thread ----
    // piece u: stage row r=u>>2 (0..255), granule q=u&3 ; rows 0..127 -> batch b0, 128..255 -> b0+1
    const int r0p = tid >> 2, q0p = tid & 3;                  // piece 0: rows 0..127
    const int r1p = r0p + 128;                                // piece 1: rows 128..255
    const uint32_t a_d0 = (uint32_t)(r0p * KC + 4 * q0p) * 4;
    const uint32_t a_d1 = (uint32_t)(r1p * KC + 4 * q0p) * 4;
    const float* a_s0 = hidden + (long)b0 * Sn * Dn + (long)r0p * Dn + 4 * q0p;
    const float* a_s1 = hidden + (long)(b0 + 1) * Sn * Dn + (long)r0p * Dn + 4 * q0p;
    const int  brw = tid >> 1, bq = tid & 1;
    const uint32_t b_d = (uint32_t)(brw * BROW + 8 * bq) * 2;
    const __nv_bfloat16* b_s = g_Wb + brw * Dn + 8 * bq;

    auto issueAB = [&](int ci, int buf) {
        cp16(a_base + (uint32_t)(buf * AST * 4) + a_d0, a_s0 + ci * KC);
        cp16(a_base + (uint32_t)(buf * AST * 4) + a_d1, a_s1 + ci * KC);
        if (tid < 112)
            cp16(b_base + (uint32_t)(buf * BST * 2) + b_d, b_s + ci * KC);
        asm volatile("cp.async.commit_group;\n");
    };

    issueAB(0, 0); issueAB(1, 1); issueAB(2, 2); issueAB(3, 3);

    // ---- stable compaction order for BOTH rows (overlaps with first loads) ----
    if (tid < 256) {
        int r2 = tid >> 7, t = tid & 127;
        int nz = (x[(b0 + r2) * Sn + t] != 0);
        unsigned m = __ballot_sync(0xFFFFFFFFu, nz);
        if (lane == 0) maskw[warp] = m;       // warps 0-3: row0, warps 4-7: row1
    }
    __syncthreads();
    if (tid < 256) {
        int r2 = tid >> 7, t = tid & 127;
        int w0 = r2 * 4;
        unsigned mw = maskw[warp];
        int nzbefore = __popc(mw & ((1u << lane) - 1u));
        int before = 0, total = 0;
        #pragma unroll
        for (int w = 0; w < 4; w++) { if (w0 + w < warp) before += __popc(maskw[w0 + w]); total += __popc(maskw[w0 + w]); }
        int isnz = (mw >> lane) & 1;
        int pos = isnz ? (before + nzbefore)
                       : (total + (t - before - nzbefore));
        order2[r2][pos] = t;
        if (t == 0) sh_len2[r2] = total;
    }

    // ---- GEMM mainloop: 48 chunks x 16KB, 5 buffers, prefetch distance 4 ----
    float acc[7][4];
    #pragma unroll
    for (int j = 0; j < 7; j++)
        #pragma unroll
        for (int q = 0; q < 4; q++) acc[j][q] = 0.0f;

    const int rowA = warp * 16 + g;            // 0..255 across both batch rows
    const uint32_t a_off0 = (uint32_t)(rowA * KC + 4 * t4);
    const uint32_t a_off1 = a_off0 + 8 * KC;

    auto computeChunk = [&](int buf) {
        const float* Abuf = As + buf * AST;
        const __nv_bfloat16* Bbuf = Bsm + buf * BST;
        float4 f0 = *(const float4*)(Abuf + a_off0);
        float4 f1 = *(const float4*)(Abuf + a_off1);
        uint32_t a0 = f2bf2(f0.x, f0.y), a2 = f2bf2(f0.z, f0.w);
        uint32_t a1 = f2bf2(f1.x, f1.y), a3 = f2bf2(f1.z, f1.w);
        #pragma unroll
        for (int j = 0; j < 7; j++) {
            uint2 bb = *(const uint2*)(Bbuf + (8 * j + g) * BROW + 4 * t4);
            asm volatile(
                "mma.sync.aligned.m16n8k16.row.col.f32.bf16.bf16.f32 "
                "{%0,%1,%2,%3}, {%4,%5,%6,%7}, {%8,%9}, {%0,%1,%2,%3};\n"
                : "+f"(acc[j][0]), "+f"(acc[j][1]), "+f"(acc[j][2]), "+f"(acc[j][3])
                : "r"(a0), "r"(a1), "r"(a2), "r"(a3), "r"(bb.x), "r"(bb.y));
        }
    };

    int buf = 0;        // buffer of chunk ci
    int bufN = 4;       // buffer of chunk ci+4
    #pragma unroll 1
    for (int ci = 0; ci < NCHUNK - 4; ci++) {
        asm volatile("cp.async.wait_group 3;\n" ::: "memory");
        __syncthreads();
        issueAB(ci + 4, bufN);
        computeChunk(buf);
        if (++buf == NBUF) buf = 0;
        if (++bufN == NBUF) bufN = 0;
    }
    // tail: chunks 44..47 in buffers 4,0,1,2 (44 % 5 == 4)
    asm volatile("cp.async.wait_group 3;\n" ::: "memory");
    __syncthreads();
    computeChunk(4);
    asm volatile("cp.async.wait_group 2;\n" ::: "memory");
    __syncthreads();
    computeChunk(0);
    asm volatile("cp.async.wait_group 1;\n" ::: "memory");
    __syncthreads();
    computeChunk(1);
    asm volatile("cp.async.wait_group 0;\n" ::: "memory");
    __syncthreads();
    computeChunk(2);

    // ---- all warps done with As before Psm overwrites it ----
    __syncthreads();
    #pragma unroll
    for (int j = 0; j < 7; j++) {
        int c = j * 8 + 2 * t4;
        Psm[rowA][c]         = acc[j][0];
        Psm[rowA][c + 1]     = acc[j][1];
        Psm[rowA + 8][c]     = acc[j][2];
        Psm[rowA + 8][c + 1] = acc[j][3];
    }
    __syncthreads();

    // ---- ragged conv + max-pool: 16 features x 2 rows, warp = feature ----
    #pragma unroll 1
    for (int r2 = 0; r2 < 2; r2++) {
        const int L = sh_len2[r2];
        const int prow = r2 * Sn;
        int fi = warp;                         // 0..15
        int kk = fi / 4 + 2;
        int f  = fi % 4;
        int cb = (kk == 2 ? 0 : (kk == 3 ? 8 : (kk == 4 ? 20 : 36))) + f * kk;
        const float* bptr = (kk == 2 ? b2 : (kk == 3 ? b3 : (kk == 4 ? b4 : b5)));
        float bias = bptr[f];
        int nt = L - kk + 1;
        float m = -1e30f;
        for (int tp = lane; tp < nt; tp += 32) {
            float sconv = bias;
            for (int j = 0; j < kk; j++)
                sconv += Psm[prow + order2[r2][tp + j]][cb + j];
            m = fmaxf(m, sconv);
        }
        #pragma unroll
        for (int off = 16; off; off >>= 1)
            m = fmaxf(m, __shfl_xor_sync(0xFFFFFFFFu, m, off));
        if (lane == 0) feats2[r2][fi] = m;
    }
    __syncthreads();

    if (tid < 2) {
        float z = fcb[0];
        #pragma unroll
        for (int i = 0; i < 16; i++) z += feats2[tid][i] * fcw[i];
        out[b0 + tid] = 1.0f / (1.0f + expf(-z));
    }
}

extern "C" void kernel_launch(void* const* d_in, const int* in_sizes, int n_in,
                              void* d_out, int out_size) {
    const int*   x      = (const int*)d_in[0];
    const float* hidden = (const float*)d_in[1];
    const float* w2     = (const float*)d_in[2];
    const float* b2     = (const float*)d_in[3];
    const float* w3     = (const float*)d_in[4];
    const float* b3     = (const float*)d_in[5];
    const float* w4     = (const float*)d_in[6];
    const float* b4     = (const float*)d_in[7];
    const float* w5     = (const float*)d_in[8];
    const float* b5     = (const float*)d_in[9];
    const float* fcw    = (const float*)d_in[10];
    const float* fcb    = (const float*)d_in[11];
    float* out = (float*)d_out;

    cudaFuncSetAttribute(fused_kernel, cudaFuncAttributeMaxDynamicSharedMemorySize, SMEM_DYN);

    build_w_kernel<<<(Cn * Dn + 255) / 256, 256>>>(w2, w3, w4, w5);
    fused_kernel<<<Bn / 2, THREADS, SMEM_DYN>>>(x, hidden, b2, b3, b4, b5, fcw, fcb, out);
}

// round 16
// speedup vs baseline: 1.4580x; 1.1369x over previous
#include <cuda_runtime.h>
#include <cuda_bf16.h>
#include <cstdint>

#define Bn 1024
#define Sn 128
#define Dn 768
#define Cn 56
#define KC 16
#define NCHUNK 48
#define NWIN 24
#define ANB 6
#define BNB 4
#define AST 2048                       /* floats per A chunk stage (8KB) */
#define BST 896                        /* bf16 per B chunk stage (1792B) */
#define A_BYTES (ANB * AST * 4)        /* 49152 */
#define B_BYTES (BNB * BST * 2)        /* 7168  */
#define SMEM_DYN (A_BYTES + B_BYTES)   /* 56320; +0 static +1024 resv = 57344 = R8 alloc */

// Raw bf16 weight matrix W[c][k], physical k order.
// Fragment mapping: a0/bb.x <-> phys cols {4t4,4t4+1}, a2/bb.y <-> {4t4+2,4t4+3}.
__device__ __nv_bfloat16 g_Wb[Cn * Dn];

__global__ void build_w_kernel(const float* __restrict__ w2, const float* __restrict__ w3,
                               const float* __restrict__ w4, const float* __restrict__ w5) {
    int i = blockIdx.x * blockDim.x + threadIdx.x;
    if (i >= Cn * Dn) return;
    int c = i / Dn, d = i % Dn;
    float v;
    if (c < 8)       { int f = c / 2;        int j = c % 2;        v = w2[(f * Dn + d) * 2 + j]; }
    else if (c < 20) { int cc = c - 8;  int f = cc / 3; int j = cc % 3; v = w3[(f * Dn + d) * 3 + j]; }
    else if (c < 36) { int cc = c - 20; int f = cc / 4; int j = cc % 4; v = w4[(f * Dn + d) * 4 + j]; }
    else             { int cc = c - 36; int f = cc / 5; int j = cc % 5; v = w5[(f * Dn + d) * 5 + j]; }
    g_Wb[c * Dn + d] = __float2bfloat16(v);
}

__device__ __forceinline__ uint32_t f2bf2(float lo, float hi) {
    __nv_bfloat162 h = __float22bfloat162_rn(make_float2(lo, hi));
    return *reinterpret_cast<uint32_t*>(&h);
}

__device__ __forceinline__ void cp16(uint32_t dst_smem, const void* src) {
    asm volatile("cp.async.cg.shared.global [%0], [%1], 16;\n" :: "r"(dst_smem), "l"(src));
}

__global__ __launch_bounds__(256, 4) void fused_kernel(
    const int* __restrict__ x, const float* __restrict__ hidden,
    const float* __restrict__ b2, const float* __restrict__ b3,
    const float* __restrict__ b4, const float* __restrict__ b5,
    const float* __restrict__ fcw, const float* __restrict__ fcb,
    float* __restrict__ out)
{
    extern __shared__ __align__(16) unsigned char sraw[];
    float* As = reinterpret_cast<float*>(sraw);                            // [ANB][128][16]
    __nv_bfloat16* Bsm = reinterpret_cast<__nv_bfloat16*>(sraw + A_BYTES); // [BNB][56][16]
    // epilogue scratch aliases the A region (all epilogue-only; NO static smem):
    float (*Psm)[Cn + 1] = reinterpret_cast<float (*)[Cn + 1]>(sraw);      // 29184B
    int*      order = reinterpret_cast<int*>(sraw + 29184);                // 512B
    unsigned* maskw = reinterpret_cast<unsigned*>(sraw + 29696);           // 16B
    int*      slen  = reinterpret_cast<int*>(sraw + 29712);                // 4B
    float*    feats = reinterpret_cast<float*>(sraw + 29720);              // 64B

    const int b    = blockIdx.x;
    const int tid  = threadIdx.x;
    const int warp = tid >> 5;
    const int lane = tid & 31;
    const int g    = lane >> 2;   // 0..7
    const int t4   = lane & 3;    // 0..3

    const uint32_t a_base = (uint32_t)__cvta_generic_to_shared(As);
    const uint32_t b_base = (uint32_t)__cvta_generic_to_shared(Bsm);
    const float* hidb = hidden + (long)b * Sn * Dn;

    // A staging (warps 0-6 = 224 threads): pieces p = tid + 224k, k<5, p<1024.
    // p -> gran = tid&3 (const), rowk = (tid>>2)+56k; half = rowk>>7, rw = rowk&127.
    const int rb   = tid >> 2;
    const int gran = tid & 3;
    const float* a_srcb = hidb + gran * 4;

    auto issueA = [&](int cA, int ab0, int ab1) {   // stages chunks cA (->ab0), cA+1 (->ab1)
        #pragma unroll
        for (int k = 0; k < 5; k++) {
            int rowk = rb + 56 * k;
            if (rowk < 256) {
                int half = rowk >> 7;
                int rw   = rowk & 127;
                int ci   = cA + half;
                if (ci < NCHUNK) {
                    int ab = half ? ab1 : ab0;
                    cp16(a_base + (uint32_t)(ab * 8192 + rw * 64 + gran * 16),
                         a_srcb + (long)rw * Dn + ci * KC);
                }
            }
        }
        asm volatile("cp.async.commit_group;\n");
    };

    // B staging (warp 7 only): 224 pieces, 7 per lane.
    auto issueB = [&](int cB, int bb0, int bb1) {
        #pragma unroll
        for (int m = 0; m < 7; m++) {
            int q = lane + 32 * m;
            int half = (q >= 112) ? 1 : 0;
            int qq = q - half * 112;
            int brw = qq >> 1, bq = qq & 1;
            int ci = cB + half;
            if (ci < NCHUNK) {
                int bb = half ? bb1 : bb0;
                cp16(b_base + (uint32_t)(bb * 1792 + brw * 32 + bq * 16),
                     g_Wb + brw * Dn + bq * 8 + ci * KC);
            }
        }
        asm volatile("cp.async.commit_group;\n");
    };

    // prologue: A two groups ahead, B one group ahead
    if (warp < 7) { issueA(0, 0, 1); issueA(2, 2, 3); }
    else          { issueB(0, 0, 1); }

    // ---- GEMM mainloop: 24 pair-windows, ONE barrier each ----
    float acc[7][4];
    #pragma unroll
    for (int j = 0; j < 7; j++)
        #pragma unroll
        for (int q = 0; q < 4; q++) acc[j][q] = 0.0f;

    const int rowA = warp * 16 + g;
    const uint32_t a_off0 = (uint32_t)(rowA * KC + 4 * t4);
    const uint32_t a_off1 = a_off0 + 8 * KC;

    auto computeChunk = [&](int ab, int bb) {
        const float* Abuf = As + ab * AST;
        const __nv_bfloat16* Bbuf = Bsm + bb * BST;
        float4 f0 = *(const float4*)(Abuf + a_off0);
        float4 f1 = *(const float4*)(Abuf + a_off1);
        uint32_t a0 = f2bf2(f0.x, f0.y), a2 = f2bf2(f0.z, f0.w);
        uint32_t a1 = f2bf2(f1.x, f1.y), a3 = f2bf2(f1.z, f1.w);
        #pragma unroll
        for (int j = 0; j < 7; j++) {
            uint2 bbv = *(const uint2*)(Bbuf + (8 * j + g) * 16 + 4 * t4);
            asm volatile(
                "mma.sync.aligned.m16n8k16.row.col.f32.bf16.bf16.f32 "
                "{%0,%1,%2,%3}, {%4,%5,%6,%7}, {%8,%9}, {%0,%1,%2,%3};\n"
                : "+f"(acc[j][0]), "+f"(acc[j][1]), "+f"(acc[j][2]), "+f"(acc[j][3])
                : "r"(a0), "r"(a1), "r"(a2), "r"(a3), "r"(bbv.x), "r"(bbv.y));
        }
    };

    int ra0 = 0;   // A buffer of chunk 2w  ( = 2w % 6 )
    int rb0 = 0;   // B buffer of chunk 2w  ( = 2w % 4 ; alternates 0,2 )
    #pragma unroll 1
    for (int w = 0; w < NWIN; w++) {
        if (warp < 7) asm volatile("cp.async.wait_group 1;\n" ::: "memory");
        else          asm volatile("cp.async.wait_group 0;\n" ::: "memory");
        __syncthreads();

        // issue next stages (buffers held chunks 2w-2, 2w-1: consumed last window)
        int iA0 = ra0 + 4; if (iA0 >= ANB) iA0 -= ANB;
        int iA1 = iA0 + 1; if (iA1 >= ANB) iA1 -= ANB;
        if (warp < 7) issueA(2 * w + 4, iA0, iA1);
        else          issueB(2 * w + 2, rb0 ^ 2, (rb0 ^ 2) + 1);

        computeChunk(ra0, rb0);
        int ra1 = ra0 + 1; if (ra1 >= ANB) ra1 -= ANB;
        computeChunk(ra1, rb0 + 1);

        ra0 += 2; if (ra0 >= ANB) ra0 -= ANB;
        rb0 ^= 2;
    }
    asm volatile("cp.async.wait_group 0;\n" ::: "memory");   // retire trailing empty groups

    // ---- epilogue (A/B regions now dead -> scratch aliasing safe after barrier) ----
    __syncthreads();
    #pragma unroll
    for (int j = 0; j < 7; j++) {
        int c = j * 8 + 2 * t4;
        Psm[rowA][c]         = acc[j][0];
        Psm[rowA][c + 1]     = acc[j][1];
        Psm[rowA + 8][c]     = acc[j][2];
        Psm[rowA + 8][c + 1] = acc[j][3];
    }
    if (tid < Sn) {
        int nz = (x[b * Sn + tid] != 0);
        unsigned m = __ballot_sync(0xFFFFFFFFu, nz);
        if (lane == 0) maskw[warp] = m;
    }
    __syncthreads();

    if (tid < Sn) {
        unsigned mw = maskw[warp];
        int nzbefore = __popc(mw & ((1u << lane) - 1u));
        int before = 0, total = 0;
        #pragma unroll
        for (int w = 0; w < 4; w++) { if (w < warp) before += __popc(maskw[w]); total += __popc(maskw[w]); }
        int isnz = (mw >> lane) & 1;
        int pos = isnz ? (before + nzbefore)
                       : (total + (tid - before - nzbefore));
        order[pos] = tid;
        if (tid == 0) *slen = total;
    }
    __syncthreads();

    // ragged conv + max-pool: 16 features, 2 per warp
    const int L = *slen;
    #pragma unroll
    for (int r = 0; r < 2; r++) {
        int fi = warp + r * 8;
        int kk = fi / 4 + 2;
        int f  = fi % 4;
        int cb = (kk == 2 ? 0 : (kk == 3 ? 8 : (kk == 4 ? 20 : 36))) + f * kk;
        const float* bptr = (kk == 2 ? b2 : (kk == 3 ? b3 : (kk == 4 ? b4 : b5)));
        float bias = bptr[f];
        int nt = L - kk + 1;
        float m = -1e30f;
        for (int tp = lane; tp < nt; tp += 32) {
            float sconv = bias;
            for (int j = 0; j < kk; j++)
                sconv += Psm[order[tp + j]][cb + j];
            m = fmaxf(m, sconv);
        }
        #pragma unroll
        for (int off = 16; off; off >>= 1)
            m = fmaxf(m, __shfl_xor_sync(0xFFFFFFFFu, m, off));
        if (lane == 0) feats[fi] = m;
    }
    __syncthreads();

    if (tid == 0) {
        float z = fcb[0];
        #pragma unroll
        for (int i = 0; i < 16; i++) z += feats[i] * fcw[i];
        out[b] = 1.0f / (1.0f + expf(-z));
    }
}

extern "C" void kernel_launch(void* const* d_in, const int* in_sizes, int n_in,
                              void* d_out, int out_size) {
    const int*   x      = (const int*)d_in[0];
    const float* hidden = (const float*)d_in[1];
    const float* w2     = (const float*)d_in[2];
    const float* b2     = (const float*)d_in[3];
    const float* w3     = (const float*)d_in[4];
    const float* b3     = (const float*)d_in[5];
    const float* w4     = (const float*)d_in[6];
    const float* b4     = (const float*)d_in[7];
    const float* w5     = (const float*)d_in[8];
    const float* b5     = (const float*)d_in[9];
    const float* fcw    = (const float*)d_in[10];
    const float* fcb    = (const float*)d_in[11];
    float* out = (float*)d_out;

    cudaFuncSetAttribute(fused_kernel, cudaFuncAttributeMaxDynamicSharedMemorySize, SMEM_DYN);

    build_w_kernel<<<(Cn * Dn + 255) / 256, 256>>>(w2, w3, w4, w5);
    fused_kernel<<<Bn, 256, SMEM_DYN>>>(x, hidden, b2, b3, b4, b5, fcw, fcb, out);
}

// round 17
// speedup vs baseline: 1.6728x; 1.1473x over previous
#include <cuda_runtime.h>
#include <cuda.h>
#include <cuda_bf16.h>
#include <cstdint>

#define Bn 1024
#define Sn 128
#define Dn 768
#define Cn 56
#define KC 16
#define NCHUNK 48
#define NBUF 5
#define AST 2048                        /* floats per A stage (8192B) */
#define A_STAGE_BYTES 8192
#define B_STAGE_BYTES 1792              /* 56 rows x 16 bf16 (32B) */
#define A_BYTES (NBUF * A_STAGE_BYTES)  /* 40960 */
#define B_BYTES (NBUF * B_STAGE_BYTES)  /* 8960  */
#define MBAR_OFF (A_BYTES + B_BYTES)    /* 49920 */
#define SMEM_DYN (MBAR_OFF + 64)        /* 49984 -> 4 CTAs/SM */
#define TX_BYTES (A_STAGE_BYTES + B_STAGE_BYTES)

// Raw bf16 weight matrix W[c][k], physical k order, 16B-aligned for TMA.
// Fragment mapping: a0/bb.x <-> phys cols {4t4,4t4+1}, a2/bb.y <-> {4t4+2,4t4+3}.
__device__ __align__(128) __nv_bfloat16 g_Wb[Cn * Dn];

__global__ void build_w_kernel(const float* __restrict__ w2, const float* __restrict__ w3,
                               const float* __restrict__ w4, const float* __restrict__ w5) {
    int i = blockIdx.x * blockDim.x + threadIdx.x;
    if (i >= Cn * Dn) return;
    int c = i / Dn, d = i % Dn;
    float v;
    if (c < 8)       { int f = c / 2;        int j = c % 2;        v = w2[(f * Dn + d) * 2 + j]; }
    else if (c < 20) { int cc = c - 8;  int f = cc / 3; int j = cc % 3; v = w3[(f * Dn + d) * 3 + j]; }
    else if (c < 36) { int cc = c - 20; int f = cc / 4; int j = cc % 4; v = w4[(f * Dn + d) * 4 + j]; }
    else             { int cc = c - 36; int f = cc / 5; int j = cc % 5; v = w5[(f * Dn + d) * 5 + j]; }
    g_Wb[c * Dn + d] = __float2bfloat16(v);
}

__device__ __forceinline__ uint32_t f2bf2(float lo, float hi) {
    __nv_bfloat162 h = __float22bfloat162_rn(make_float2(lo, hi));
    return *reinterpret_cast<uint32_t*>(&h);
}

__device__ __forceinline__ void mbar_init(uint32_t addr, uint32_t count) {
    asm volatile("mbarrier.init.shared.b64 [%0], %1;" :: "r"(addr), "r"(count) : "memory");
}
__device__ __forceinline__ void mbar_expect_tx(uint32_t addr, uint32_t bytes) {
    asm volatile("mbarrier.arrive.expect_tx.shared.b64 _, [%0], %1;" :: "r"(addr), "r"(bytes) : "memory");
}
__device__ __forceinline__ void mbar_wait(uint32_t addr, uint32_t parity) {
    uint32_t done;
    asm volatile(
        "{\n\t.reg .pred p;\n\t"
        "mbarrier.try_wait.parity.acquire.cta.shared::cta.b64 p, [%1], %2;\n\t"
        "selp.b32 %0, 1, 0, p;\n\t}"
        : "=r"(done) : "r"(addr), "r"(parity) : "memory");
    if (!done) {
        asm volatile(
            "{\n\t.reg .pred P1;\n\t"
            "WAIT_LOOP_%=:\n\t"
            "mbarrier.try_wait.parity.acquire.cta.shared::cta.b64 P1, [%0], %1, 0x989680;\n\t"
            "@P1 bra.uni WAIT_DONE_%=;\n\t"
            "bra.uni WAIT_LOOP_%=;\n\t"
            "WAIT_DONE_%=:\n\t}"
            :: "r"(addr), "r"(parity) : "memory");
    }
}
__device__ __forceinline__ void tma_load_2d(uint32_t smem_addr, const CUtensorMap* map,
                                            int cx, int cy, uint32_t mbar) {
    asm volatile(
        "cp.async.bulk.tensor.2d.shared::cta.global.tile.mbarrier::complete_tx::bytes "
        "[%0], [%1, {%2, %3}], [%4];"
        :: "r"(smem_addr), "l"(map), "r"(cx), "r"(cy), "r"(mbar) : "memory");
}

__global__ __launch_bounds__(256, 4) void fused_kernel(
    const __grid_constant__ CUtensorMap tmA,
    const __grid_constant__ CUtensorMap tmB,
    const int* __restrict__ x,
    const float* __restrict__ b2, const float* __restrict__ b3,
    const float* __restrict__ b4, const float* __restrict__ b5,
    const float* __restrict__ fcw, const float* __restrict__ fcb,
    float* __restrict__ out)
{
    extern __shared__ __align__(128) unsigned char sraw[];
    float* As = reinterpret_cast<float*>(sraw);                            // [NBUF][128][16]
    __nv_bfloat16* Bsm = reinterpret_cast<__nv_bfloat16*>(sraw + A_BYTES); // [NBUF][56][16]
    float (*Psm)[Cn + 1] = reinterpret_cast<float (*)[Cn + 1]>(sraw);      // epilogue reuse (29184B)

    __shared__ int order[Sn];
    __shared__ unsigned maskw[8];
    __shared__ int sh_len;
    __shared__ float feats[16];

    const int b    = blockIdx.x;
    const int tid  = threadIdx.x;
    const int warp = tid >> 5;
    const int lane = tid & 31;
    const int g    = lane >> 2;   // 0..7
    const int t4   = lane & 3;    // 0..3

    const uint32_t smem_base = (uint32_t)__cvta_generic_to_shared(sraw);
    const uint32_t mbar0 = smem_base + MBAR_OFF;

    // ---- init mbarriers (count=1: the expect_tx arrive) ----
    if (tid == 0) {
        #pragma unroll
        for (int s = 0; s < NBUF; s++) mbar_init(mbar0 + 8 * s, 1);
        asm volatile("fence.proxy.async.shared::cta;" ::: "memory");
    }
    __syncthreads();

    // ---- prologue: issue chunks 0..3 (single thread, fully async) ----
    if (tid == 0) {
        #pragma unroll
        for (int c = 0; c < 4; c++) {
            mbar_expect_tx(mbar0 + 8 * c, TX_BYTES);
            tma_load_2d(smem_base + c * A_STAGE_BYTES, &tmA, c * KC, b * Sn, mbar0 + 8 * c);
            tma_load_2d(smem_base + A_BYTES + c * B_STAGE_BYTES, &tmB, c * KC, 0, mbar0 + 8 * c);
        }
    }

    // ---- stable compaction order (overlaps with TMA prologue) ----
    if (tid < Sn) {
        int nz = (x[b * Sn + tid] != 0);
        unsigned m = __ballot_sync(0xFFFFFFFFu, nz);
        if (lane == 0) maskw[warp] = m;
    }
    __syncthreads();
    if (tid < Sn) {
        unsigned mw = maskw[warp];
        int nzbefore = __popc(mw & ((1u << lane) - 1u));
        int before = 0, total = 0;
        #pragma unroll
        for (int w = 0; w < 4; w++) { if (w < warp) before += __popc(maskw[w]); total += __popc(maskw[w]); }
        int isnz = (mw >> lane) & 1;
        int pos = isnz ? (before + nzbefore)
                       : (total + (tid - before - nzbefore));
        order[pos] = tid;
        if (tid == 0) sh_len = total;
    }

    // ---- GEMM mainloop: 48 chunks, 5 slots, prefetch distance 4, TMA-fed ----
    float acc[7][4];
    #pragma unroll
    for (int j = 0; j < 7; j++)
        #pragma unroll
        for (int q = 0; q < 4; q++) acc[j][q] = 0.0f;

    const int rowA = warp * 16 + g;
    const uint32_t a_off0 = (uint32_t)(rowA * KC + 4 * t4);
    const uint32_t a_off1 = a_off0 + 8 * KC;

    int slot = 0, par = 0;
    #pragma unroll 1
    for (int ci = 0; ci < NCHUNK; ci++) {
        mbar_wait(mbar0 + 8 * slot, par);    // chunk ci landed (acquire)
        __syncthreads();                     // all warps finished reading chunk ci-1

        if (tid == 0 && ci + 4 < NCHUNK) {
            int s2 = slot + 4; if (s2 >= NBUF) s2 -= NBUF;   // slot of ci+4 (= slot of ci-1)
            mbar_expect_tx(mbar0 + 8 * s2, TX_BYTES);
            tma_load_2d(smem_base + s2 * A_STAGE_BYTES, &tmA, (ci + 4) * KC, b * Sn, mbar0 + 8 * s2);
            tma_load_2d(smem_base + A_BYTES + s2 * B_STAGE_BYTES, &tmB, (ci + 4) * KC, 0, mbar0 + 8 * s2);
        }

        const float* Abuf = As + slot * AST;
        const __nv_bfloat16* Bbuf = Bsm + slot * (B_STAGE_BYTES / 2);
        float4 f0 = *(const float4*)(Abuf + a_off0);
        float4 f1 = *(const float4*)(Abuf + a_off1);
        uint32_t a0 = f2bf2(f0.x, f0.y), a2 = f2bf2(f0.z, f0.w);
        uint32_t a1 = f2bf2(f1.x, f1.y), a3 = f2bf2(f1.z, f1.w);
        #pragma unroll
        for (int j = 0; j < 7; j++) {
            uint2 bb = *(const uint2*)(Bbuf + (8 * j + g) * 16 + 4 * t4);
            asm volatile(
                "mma.sync.aligned.m16n8k16.row.col.f32.bf16.bf16.f32 "
                "{%0,%1,%2,%3}, {%4,%5,%6,%7}, {%8,%9}, {%0,%1,%2,%3};\n"
                : "+f"(acc[j][0]), "+f"(acc[j][1]), "+f"(acc[j][2]), "+f"(acc[j][3])
                : "r"(a0), "r"(a1), "r"(a2), "r"(a3), "r"(bb.x), "r"(bb.y));
        }

        if (++slot == NBUF) { slot = 0; par ^= 1; }
    }

    // ---- all warps done with As before Psm overwrites it ----
    __syncthreads();
    #pragma unroll
    for (int j = 0; j < 7; j++) {
        int c = j * 8 + 2 * t4;
        Psm[rowA][c]         = acc[j][0];
        Psm[rowA][c + 1]     = acc[j][1];
        Psm[rowA + 8][c]     = acc[j][2];
        Psm[rowA + 8][c + 1] = acc[j][3];
    }
    __syncthreads();

    // ---- ragged conv + max-pool: 16 features, 2 per warp ----
    const int L = sh_len;
    #pragma unroll
    for (int r = 0; r < 2; r++) {
        int fi = warp + r * 8;
        int kk = fi / 4 + 2;
        int f  = fi % 4;
        int cb = (kk == 2 ? 0 : (kk == 3 ? 8 : (kk == 4 ? 20 : 36))) + f * kk;
        const float* bptr = (kk == 2 ? b2 : (kk == 3 ? b3 : (kk == 4 ? b4 : b5)));
        float bias = bptr[f];
        int nt = L - kk + 1;
        float m = -1e30f;
        for (int tp = lane; tp < nt; tp += 32) {
            float sconv = bias;
            for (int j = 0; j < kk; j++)
                sconv += Psm[order[tp + j]][cb + j];
            m = fmaxf(m, sconv);
        }
        #pragma unroll
        for (int off = 16; off; off >>= 1)
            m = fmaxf(m, __shfl_xor_sync(0xFFFFFFFFu, m, off));
        if (lane == 0) feats[fi] = m;
    }
    __syncthreads();

    if (tid == 0) {
        float z = fcb[0];
        #pragma unroll
        for (int i = 0; i < 16; i++) z += feats[i] * fcw[i];
        out[b] = 1.0f / (1.0f + expf(-z));
    }
}

typedef CUresult (*EncodeTiledFn)(
    CUtensorMap*, CUtensorMapDataType, cuuint32_t, void*,
    const cuuint64_t*, const cuuint64_t*, const cuuint32_t*, const cuuint32_t*,
    CUtensorMapInterleave, CUtensorMapSwizzle, CUtensorMapL2promotion, CUtensorMapFloatOOBfill);

extern "C" void kernel_launch(void* const* d_in, const int* in_sizes, int n_in,
                              void* d_out, int out_size) {
    const int*   x      = (const int*)d_in[0];
    const float* hidden = (const float*)d_in[1];
    const float* w2     = (const float*)d_in[2];
    const float* b2     = (const float*)d_in[3];
    const float* w3     = (const float*)d_in[4];
    const float* b3     = (const float*)d_in[5];
    const float* w4     = (const float*)d_in[6];
    const float* b4     = (const float*)d_in[7];
    const float* w5     = (const float*)d_in[8];
    const float* b5     = (const float*)d_in[9];
    const float* fcw    = (const float*)d_in[10];
    const float* fcb    = (const float*)d_in[11];
    float* out = (float*)d_out;

    // fetch cuTensorMapEncodeTiled via runtime (no -lcuda link dependency)
    EncodeTiledFn enc = nullptr;
    cudaDriverEntryPointQueryResult qr;
    cudaGetDriverEntryPoint("cuTensorMapEncodeTiled", (void**)&enc, cudaEnableDefault, &qr);

    void* wb_ptr = nullptr;
    cudaGetSymbolAddress(&wb_ptr, g_Wb);

    CUtensorMap tmA{}, tmB{};
    {
        cuuint64_t dims[2]    = {(cuuint64_t)Dn, (cuuint64_t)Bn * Sn};
        cuuint64_t strides[1] = {(cuuint64_t)Dn * sizeof(float)};
        cuuint32_t box[2]     = {KC, Sn};
        cuuint32_t es[2]      = {1, 1};
        enc(&tmA, CU_TENSOR_MAP_DATA_TYPE_FLOAT32, 2, (void*)hidden,
            dims, strides, box, es,
            CU_TENSOR_MAP_INTERLEAVE_NONE, CU_TENSOR_MAP_SWIZZLE_NONE,
            CU_TENSOR_MAP_L2_PROMOTION_L2_128B, CU_TENSOR_MAP_FLOAT_OOB_FILL_NONE);
    }
    {
        cuuint64_t dims[2]    = {(cuuint64_t)Dn, (cuuint64_t)Cn};
        cuuint64_t strides[1] = {(cuuint64_t)Dn * sizeof(__nv_bfloat16)};
        cuuint32_t box[2]     = {KC, Cn};
        cuuint32_t es[2]      = {1, 1};
        enc(&tmB, CU_TENSOR_MAP_DATA_TYPE_BFLOAT16, 2, wb_ptr,
            dims, strides, box, es,
            CU_TENSOR_MAP_INTERLEAVE_NONE, CU_TENSOR_MAP_SWIZZLE_NONE,
            CU_TENSOR_MAP_L2_PROMOTION_L2_128B, CU_TENSOR_MAP_FLOAT_OOB_FILL_NONE);
    }

    cudaFuncSetAttribute(fused_kernel, cudaFuncAttributeMaxDynamicSharedMemorySize, SMEM_DYN);

    build_w_kernel<<<(Cn * Dn + 255) / 256, 256>>>(w2, w3, w4, w5);
    fused_kernel<<<Bn, 256, SMEM_DYN>>>(tmA, tmB, x, b2, b3, b4, b5, fcw, fcb, out);
}